// round 7
// baseline (speedup 1.0000x reference)
#include <cuda_runtime.h>
#include <cuda_fp16.h>
#include <cstdint>

#define T_TOK 8192
#define HDIM  1024
#define NEXP  8
#define TPAD  (T_TOK + NEXP*128)

#define BM 128
#define BN 128
#define BK 64
#define NITER 16        // 1024 / 64
#define NSTAGE 3

// ---------------- device scratch ----------------
__device__ int   g_counts[NEXP];
__device__ int   g_offpad[NEXP + 1];
__device__ int   g_expert[T_TOK];
__device__ float g_gate[T_TOK];
__device__ int   g_tokpad[TPAD];
__device__ __half g_xh[(size_t)T_TOK * HDIM];               // token order
__device__ __half g_wh[(size_t)NEXP * HDIM * HDIM];         // [e][n][k]

// ---------------- helpers ----------------
__device__ __forceinline__ uint32_t smem_u32(const void* p) {
    uint32_t a;
    asm("{ .reg .u64 t; cvta.to.shared.u64 t, %1; cvt.u32.u64 %0, t; }" : "=r"(a) : "l"(p));
    return a;
}
__device__ __forceinline__ void cp16(uint32_t dst, const void* src) {
    asm volatile("cp.async.cg.shared.global [%0], [%1], 16;" :: "r"(dst), "l"(src));
}
__device__ __forceinline__ void cp_commit() {
    asm volatile("cp.async.commit_group;" ::: "memory");
}
template <int N>
__device__ __forceinline__ void cp_wait() {
    asm volatile("cp.async.wait_group %0;" :: "n"(N) : "memory");
}
#define LDSM4(R, addr) \
    asm volatile("ldmatrix.sync.aligned.m8n8.x4.shared.b16 {%0,%1,%2,%3}, [%4];" \
                 : "=r"((R)[0]), "=r"((R)[1]), "=r"((R)[2]), "=r"((R)[3]) : "r"(addr))
#define MMA16816(D, A, B0, B1) \
    asm volatile("mma.sync.aligned.m16n8k16.row.col.f32.f16.f16.f32 " \
                 "{%0,%1,%2,%3}, {%4,%5,%6,%7}, {%8,%9}, {%0,%1,%2,%3};" \
                 : "+f"((D)[0]), "+f"((D)[1]), "+f"((D)[2]), "+f"((D)[3]) \
                 : "r"((A)[0]), "r"((A)[1]), "r"((A)[2]), "r"((A)[3]), "r"(B0), "r"(B1))

// ---------------- phase 1: transpose + convert W -> fp16 [e][n][k] --------
// 64(k) x 128(n) tile, float4 loads
__global__ void convert_w_kernel(const float* __restrict__ ew) {
    __shared__ float tile[64][129];
    int e  = blockIdx.z;
    int k0 = blockIdx.y * 64, n0 = blockIdx.x * 128;
    int tid = threadIdx.x;                     // 256
    const float* W = ew + (size_t)e * HDIM * HDIM;
    // load 64x128 floats: 8192 elems = 2048 float4; 256 threads x 8
#pragma unroll
    for (int i = 0; i < 8; i++) {
        int op = tid + i * 256;               // float4 index
        int r = op >> 5, c = (op & 31) * 4;   // row k, col n
        float4 v = *reinterpret_cast<const float4*>(W + (size_t)(k0 + r) * HDIM + n0 + c);
        tile[r][c + 0] = v.x;
        tile[r][c + 1] = v.y;
        tile[r][c + 2] = v.z;
        tile[r][c + 3] = v.w;
    }
    __syncthreads();
    // write transposed fp16: rows n (128), each row 64 k = 32 uint32; 256 threads
    int l  = tid & 31;        // k-pair: k = 2*l
    int nr = tid >> 5;        // 0..7
    uint32_t* w32 = reinterpret_cast<uint32_t*>(g_wh);
#pragma unroll
    for (int q = 0; q < 16; q++) {
        int n = nr + q * 8;
        __half2 h = __floats2half2_rn(tile[2 * l][n], tile[2 * l + 1][n]);
        size_t idx = ((size_t)e * HDIM + (n0 + n)) * (HDIM / 2) + (k0 / 2 + l);
        w32[idx] = *reinterpret_cast<uint32_t*>(&h);
    }
}

// ---------------- phase 2: router + convert x -> fp16 ----------------
__global__ void router_kernel(const float* __restrict__ x,
                              const float* __restrict__ rw,
                              const float* __restrict__ rb) {
    int gwarp = (blockIdx.x * blockDim.x + threadIdx.x) >> 5;
    int lane  = threadIdx.x & 31;
    if (gwarp >= T_TOK) return;

    const float* xr = x + (size_t)gwarp * HDIM;
    __half* hp = g_xh + (size_t)gwarp * HDIM;
    float acc[NEXP];
#pragma unroll
    for (int e = 0; e < NEXP; e++) acc[e] = 0.f;

#pragma unroll
    for (int i = 0; i < HDIM / 128; i++) {
        int h = (i * 32 + lane) * 4;
        float4 xv = *reinterpret_cast<const float4*>(xr + h);
        __half2 c0 = __floats2half2_rn(xv.x, xv.y);
        __half2 c1 = __floats2half2_rn(xv.z, xv.w);
        uint2 pk;
        pk.x = *reinterpret_cast<uint32_t*>(&c0);
        pk.y = *reinterpret_cast<uint32_t*>(&c1);
        *reinterpret_cast<uint2*>(hp + h) = pk;

        float xa[4] = {xv.x, xv.y, xv.z, xv.w};
#pragma unroll
        for (int c = 0; c < 4; c++) {
            const float4 w0 = __ldg(reinterpret_cast<const float4*>(rw + (size_t)(h + c) * NEXP));
            const float4 w1 = __ldg(reinterpret_cast<const float4*>(rw + (size_t)(h + c) * NEXP + 4));
            float xc = xa[c];
            acc[0] += xc * w0.x; acc[1] += xc * w0.y;
            acc[2] += xc * w0.z; acc[3] += xc * w0.w;
            acc[4] += xc * w1.x; acc[5] += xc * w1.y;
            acc[6] += xc * w1.z; acc[7] += xc * w1.w;
        }
    }
#pragma unroll
    for (int e = 0; e < NEXP; e++) {
#pragma unroll
        for (int off = 16; off > 0; off >>= 1)
            acc[e] += __shfl_xor_sync(0xffffffffu, acc[e], off);
    }
    if (lane == 0) {
        float logit[NEXP];
        float best = -1e30f;
        int   bi = 0;
#pragma unroll
        for (int e = 0; e < NEXP; e++) {
            logit[e] = acc[e] + rb[e];
            if (logit[e] > best) { best = logit[e]; bi = e; }
        }
        float s = 0.f;
#pragma unroll
        for (int e = 0; e < NEXP; e++) s += expf(logit[e] - best);
        g_expert[gwarp] = bi;
        g_gate[gwarp]   = 1.0f / s;
    }
}

// ---------------- phase 3: fused counts + scan + permutation --------------
// warp-aggregated atomics: one atomicAdd per distinct expert per warp-iter
__global__ void scan_assign_kernel() {
    __shared__ int cnt[NEXP];
    __shared__ int cur[NEXP];
    int tid = threadIdx.x;
    int lane = tid & 31;
    if (tid < NEXP) cnt[tid] = 0;
    __syncthreads();
    int local[NEXP];
#pragma unroll
    for (int e = 0; e < NEXP; e++) local[e] = 0;
    for (int t = tid; t < T_TOK; t += blockDim.x) local[g_expert[t]]++;
#pragma unroll
    for (int e = 0; e < NEXP; e++)
        if (local[e]) atomicAdd(&cnt[e], local[e]);
    __syncthreads();
    if (tid == 0) {
        int o = 0;
#pragma unroll
        for (int e = 0; e < NEXP; e++) {
            g_counts[e] = cnt[e];
            g_offpad[e] = o;
            cur[e] = o;
            o += ((cnt[e] + 127) >> 7) << 7;
        }
        g_offpad[NEXP] = o;
    }
    __syncthreads();
    for (int t = tid; t < T_TOK; t += blockDim.x) {
        int e = g_expert[t];
        unsigned peers = __match_any_sync(0xffffffffu, e);
        int leader = __ffs(peers) - 1;
        int rank = __popc(peers & ((1u << lane) - 1));
        int base = 0;
        if (lane == leader) base = atomicAdd(&cur[e], __popc(peers));
        base = __shfl_sync(0xffffffffu, base, leader);
        g_tokpad[base + rank] = t;
    }
}

// ---------------- phase 4: grouped fp16 HMMA GEMM (128x128, 3-stage) -------
static constexpr uint32_t OFF_B    = 49152;   // 3 x 16KB A buffers first
static constexpr uint32_t OFF_TOK  = 98304;
static constexpr uint32_t OFF_GATE = 98816;
static constexpr uint32_t SMEM_TOTAL = 99328;

__device__ __forceinline__ void issue_stage(int j, int tid, const int* sTok, int n0,
                                            size_t ebase, uint32_t sbase) {
    int kin = j * BK;
    int buf = j % NSTAGE;
    const __half* Bb = g_wh + ebase;
    uint32_t as = sbase + (uint32_t)buf * 16384;
    uint32_t bs = sbase + OFF_B + (uint32_t)buf * 16384;
#pragma unroll
    for (int i = 0; i < 4; i++) {
        int op = tid + i * 256;
        int r = op >> 3, c = op & 7;
        cp16(as + r * 128 + ((c * 16) ^ ((r & 7) << 4)),
             g_xh + (size_t)sTok[r] * HDIM + kin + c * 8);
    }
#pragma unroll
    for (int i = 0; i < 4; i++) {
        int op = tid + i * 256;
        int r = op >> 3, c = op & 7;
        cp16(bs + r * 128 + ((c * 16) ^ ((r & 7) << 4)),
             Bb + (size_t)(n0 + r) * HDIM + kin + c * 8);
    }
    cp_commit();
}

__global__ __launch_bounds__(256, 2)
void moe_gemm_kernel(const float* __restrict__ eb, float* __restrict__ out) {
    extern __shared__ __align__(1024) char smem[];
    const int m0 = blockIdx.y * BM;
    if (m0 >= g_offpad[NEXP]) return;
    int e = 0;
    while (m0 >= g_offpad[e + 1]) e++;
    const int rows_valid = min(BM, g_offpad[e] + g_counts[e] - m0);
    const int n0 = blockIdx.x * BN;
    const int tid = threadIdx.x;
    const uint32_t sbase = smem_u32(smem);
    const size_t ebase = (size_t)e * HDIM * HDIM;
    int* sTok = (int*)(smem + OFF_TOK);
    float* sGate = (float*)(smem + OFF_GATE);

    if (tid < 128) {
        int tok = g_tokpad[m0 + tid] & (T_TOK - 1);
        sTok[tid] = tok;
        sGate[tid] = g_gate[tok];
    }
    __syncthreads();

    issue_stage(0, tid, sTok, n0, ebase, sbase);
    issue_stage(1, tid, sTok, n0, ebase, sbase);
    issue_stage(2, tid, sTok, n0, ebase, sbase);

    const int lane = tid & 31, wid = tid >> 5;
    const int warp_m = (wid >> 1) * 32;
    const int warp_n = (wid & 1) * 64;
    const int idx = lane & 7, grp = lane >> 3;

    const int arow = warp_m + (grp & 1) * 8 + idx;
    const uint32_t axor = (uint32_t)((arow & 7) << 4);
    const uint32_t acsel = (uint32_t)((grp >> 1) * 16);
    const int brow = warp_n + (grp >> 1) * 8 + idx;
    const uint32_t bxor = (uint32_t)((brow & 7) << 4);
    const uint32_t bcsel = (uint32_t)((grp & 1) * 16);

    float acc[2][8][4];
#pragma unroll
    for (int i = 0; i < 2; i++)
#pragma unroll
        for (int j = 0; j < 8; j++)
#pragma unroll
            for (int q = 0; q < 4; q++) acc[i][j][q] = 0.f;

    // double-buffered fragments for LDSM/MMA software pipelining
    uint32_t afrag[2][2][4], bfrag[2][4][4];

#define LOAD_FRAGS(slot, as_, bs_, kc_)                                           \
    do {                                                                          \
        _Pragma("unroll")                                                         \
        for (int mt = 0; mt < 2; mt++)                                            \
            LDSM4(afrag[slot][mt],                                                \
                  (as_) + (uint32_t)(arow + mt * 16) * 128 + (((kc_) + acsel) ^ axor)); \
        _Pragma("unroll")                                                         \
        for (int bt = 0; bt < 4; bt++)                                            \
            LDSM4(bfrag[slot][bt],                                                \
                  (bs_) + (uint32_t)(brow + bt * 16) * 128 + (((kc_) + bcsel) ^ bxor)); \
    } while (0)

    for (int k = 0; k < NITER; k++) {
        cp_wait<2>();
        __syncthreads();
        int buf = k % NSTAGE;
        uint32_t as = sbase + (uint32_t)buf * 16384;
        uint32_t bs = sbase + OFF_B + (uint32_t)buf * 16384;

        LOAD_FRAGS(0, as, bs, 0u);
#pragma unroll
        for (int step = 0; step < 4; step++) {
            int curb = step & 1, nxtb = curb ^ 1;
            if (step < 3)
                LOAD_FRAGS(nxtb, as, bs, (uint32_t)((step + 1) * 32));
#pragma unroll
            for (int mt = 0; mt < 2; mt++)
#pragma unroll
                for (int bt = 0; bt < 4; bt++) {
                    MMA16816(acc[mt][2 * bt],     afrag[curb][mt], bfrag[curb][bt][0], bfrag[curb][bt][1]);
                    MMA16816(acc[mt][2 * bt + 1], afrag[curb][mt], bfrag[curb][bt][2], bfrag[curb][bt][3]);
                }
        }
        __syncthreads();
        if (k + NSTAGE < NITER) issue_stage(k + NSTAGE, tid, sTok, n0, ebase, sbase);
        else cp_commit();
    }
#undef LOAD_FRAGS

    // epilogue
    const float* ebias = eb + (size_t)e * HDIM + n0;
    const int colq = (lane & 3) * 2;
#pragma unroll
    for (int mt = 0; mt < 2; mt++) {
        int r_lo = warp_m + mt * 16 + (lane >> 2);
        int r_hi = r_lo + 8;
        bool v_lo = r_lo < rows_valid, v_hi = r_hi < rows_valid;
        int   t_lo = sTok[r_lo],  t_hi = sTok[r_hi];
        float g_lo = sGate[r_lo], g_hi = sGate[r_hi];
        float* o_lo = out + (size_t)t_lo * HDIM + n0;
        float* o_hi = out + (size_t)t_hi * HDIM + n0;
#pragma unroll
        for (int nt = 0; nt < 8; nt++) {
            int col = warp_n + nt * 8 + colq;
            float2 bv = *reinterpret_cast<const float2*>(ebias + col);
            if (v_lo) {
                float2 v;
                v.x = g_lo * (acc[mt][nt][0] + bv.x);
                v.y = g_lo * (acc[mt][nt][1] + bv.y);
                *reinterpret_cast<float2*>(o_lo + col) = v;
            }
            if (v_hi) {
                float2 v;
                v.x = g_hi * (acc[mt][nt][2] + bv.x);
                v.y = g_hi * (acc[mt][nt][3] + bv.y);
                *reinterpret_cast<float2*>(o_hi + col) = v;
            }
        }
    }
}

// ---------------- launch ----------------
extern "C" void kernel_launch(void* const* d_in, const int* in_sizes, int n_in,
                              void* d_out, int out_size) {
    const float* x  = (const float*)d_in[0];
    const float* rw = (const float*)d_in[1];
    const float* rb = (const float*)d_in[2];
    const float* ew = (const float*)d_in[3];
    const float* eb = (const float*)d_in[4];
    float* out = (float*)d_out;

    cudaFuncSetAttribute(moe_gemm_kernel,
                         cudaFuncAttributeMaxDynamicSharedMemorySize, SMEM_TOTAL);

    convert_w_kernel<<<dim3(8, 16, 8), 256>>>(ew);            // 1
    router_kernel<<<T_TOK / 8, 256>>>(x, rw, rb);             // 2
    scan_assign_kernel<<<1, 256>>>();                         // 3
    moe_gemm_kernel<<<dim3(HDIM / BN, TPAD / BM), 256, SMEM_TOTAL>>>(eb, out); // 4
}

// round 8
// speedup vs baseline: 1.0256x; 1.0256x over previous
#include <cuda_runtime.h>
#include <cuda_fp16.h>
#include <cstdint>

#define T_TOK 8192
#define HDIM  1024
#define NEXP  8
#define TPAD  (T_TOK + NEXP*128)

#define BM 128
#define BN 128
#define BK 64
#define NITER 16        // 1024 / 64
#define NSTAGE 3

// ---------------- device scratch ----------------
__device__ int   g_counts[NEXP];
__device__ int   g_offpad[NEXP + 1];
__device__ int   g_expert[T_TOK];
__device__ float g_gate[T_TOK];
__device__ int   g_tokpad[TPAD];
__device__ __half g_xh[(size_t)T_TOK * HDIM];               // token order
__device__ __half g_wh[(size_t)NEXP * HDIM * HDIM];         // [e][n][k]

// ---------------- helpers ----------------
__device__ __forceinline__ uint32_t smem_u32(const void* p) {
    uint32_t a;
    asm("{ .reg .u64 t; cvta.to.shared.u64 t, %1; cvt.u32.u64 %0, t; }" : "=r"(a) : "l"(p));
    return a;
}
__device__ __forceinline__ void cp16(uint32_t dst, const void* src) {
    asm volatile("cp.async.cg.shared.global [%0], [%1], 16;" :: "r"(dst), "l"(src));
}
__device__ __forceinline__ void cp_commit() {
    asm volatile("cp.async.commit_group;" ::: "memory");
}
template <int N>
__device__ __forceinline__ void cp_wait() {
    asm volatile("cp.async.wait_group %0;" :: "n"(N) : "memory");
}
#define LDSM4(R, addr) \
    asm volatile("ldmatrix.sync.aligned.m8n8.x4.shared.b16 {%0,%1,%2,%3}, [%4];" \
                 : "=r"((R)[0]), "=r"((R)[1]), "=r"((R)[2]), "=r"((R)[3]) : "r"(addr))
#define MMA16816(D, A, B0, B1) \
    asm volatile("mma.sync.aligned.m16n8k16.row.col.f32.f16.f16.f32 " \
                 "{%0,%1,%2,%3}, {%4,%5,%6,%7}, {%8,%9}, {%0,%1,%2,%3};" \
                 : "+f"((D)[0]), "+f"((D)[1]), "+f"((D)[2]), "+f"((D)[3]) \
                 : "r"((A)[0]), "r"((A)[1]), "r"((A)[2]), "r"((A)[3]), "r"(B0), "r"(B1))

// ---------------- phase 1: transpose + convert W -> fp16 [e][n][k] --------
__global__ void convert_w_kernel(const float* __restrict__ ew) {
    __shared__ float tile[64][33];
    int e  = blockIdx.z;
    int k0 = blockIdx.y * 64, n0 = blockIdx.x * 32;
    int tx = threadIdx.x, ty = threadIdx.y;   // 32 x 8
    const float* W = ew + (size_t)e * HDIM * HDIM;
#pragma unroll
    for (int p = 0; p < 8; p++)
        tile[ty + p * 8][tx] = W[(size_t)(k0 + ty + p * 8) * HDIM + n0 + tx];
    __syncthreads();
    int tid = ty * 32 + tx;
    int l   = tid & 31;        // k-pair: k = 2*l
    int nr  = tid >> 5;        // 0..7
    uint32_t* w32 = reinterpret_cast<uint32_t*>(g_wh);
#pragma unroll
    for (int q = 0; q < 4; q++) {
        int n = nr + q * 8;
        __half2 h = __floats2half2_rn(tile[2 * l][n], tile[2 * l + 1][n]);
        size_t idx = ((size_t)e * HDIM + (n0 + n)) * (HDIM / 2) + (k0 / 2 + l);
        w32[idx] = *reinterpret_cast<uint32_t*>(&h);
    }
}

// ---------------- phase 2: router + convert x -> fp16 ----------------
__global__ void router_kernel(const float* __restrict__ x,
                              const float* __restrict__ rw,
                              const float* __restrict__ rb) {
    int gwarp = (blockIdx.x * blockDim.x + threadIdx.x) >> 5;
    int lane  = threadIdx.x & 31;
    if (gwarp >= T_TOK) return;

    const float* xr = x + (size_t)gwarp * HDIM;
    __half* hp = g_xh + (size_t)gwarp * HDIM;
    float acc[NEXP];
#pragma unroll
    for (int e = 0; e < NEXP; e++) acc[e] = 0.f;

#pragma unroll
    for (int i = 0; i < HDIM / 128; i++) {
        int h = (i * 32 + lane) * 4;
        float4 xv = *reinterpret_cast<const float4*>(xr + h);
        __half2 c0 = __floats2half2_rn(xv.x, xv.y);
        __half2 c1 = __floats2half2_rn(xv.z, xv.w);
        uint2 pk;
        pk.x = *reinterpret_cast<uint32_t*>(&c0);
        pk.y = *reinterpret_cast<uint32_t*>(&c1);
        *reinterpret_cast<uint2*>(hp + h) = pk;

        float xa[4] = {xv.x, xv.y, xv.z, xv.w};
#pragma unroll
        for (int c = 0; c < 4; c++) {
            const float4 w0 = __ldg(reinterpret_cast<const float4*>(rw + (size_t)(h + c) * NEXP));
            const float4 w1 = __ldg(reinterpret_cast<const float4*>(rw + (size_t)(h + c) * NEXP + 4));
            float xc = xa[c];
            acc[0] += xc * w0.x; acc[1] += xc * w0.y;
            acc[2] += xc * w0.z; acc[3] += xc * w0.w;
            acc[4] += xc * w1.x; acc[5] += xc * w1.y;
            acc[6] += xc * w1.z; acc[7] += xc * w1.w;
        }
    }
#pragma unroll
    for (int e = 0; e < NEXP; e++) {
#pragma unroll
        for (int off = 16; off > 0; off >>= 1)
            acc[e] += __shfl_xor_sync(0xffffffffu, acc[e], off);
    }
    if (lane == 0) {
        float logit[NEXP];
        float best = -1e30f;
        int   bi = 0;
#pragma unroll
        for (int e = 0; e < NEXP; e++) {
            logit[e] = acc[e] + rb[e];
            if (logit[e] > best) { best = logit[e]; bi = e; }
        }
        float s = 0.f;
#pragma unroll
        for (int e = 0; e < NEXP; e++) s += expf(logit[e] - best);
        g_expert[gwarp] = bi;
        g_gate[gwarp]   = 1.0f / s;
    }
}

// ---------------- phase 3: fused counts + scan + permutation --------------
__global__ void scan_assign_kernel() {
    __shared__ int cnt[NEXP];
    __shared__ int cur[NEXP];
    int tid = threadIdx.x;
    int lane = tid & 31;
    if (tid < NEXP) cnt[tid] = 0;
    __syncthreads();
    int local[NEXP];
#pragma unroll
    for (int e = 0; e < NEXP; e++) local[e] = 0;
    for (int t = tid; t < T_TOK; t += blockDim.x) local[g_expert[t]]++;
#pragma unroll
    for (int e = 0; e < NEXP; e++)
        if (local[e]) atomicAdd(&cnt[e], local[e]);
    __syncthreads();
    if (tid == 0) {
        int o = 0;
#pragma unroll
        for (int e = 0; e < NEXP; e++) {
            g_counts[e] = cnt[e];
            g_offpad[e] = o;
            cur[e] = o;
            o += ((cnt[e] + 127) >> 7) << 7;
        }
        g_offpad[NEXP] = o;
    }
    __syncthreads();
    for (int t = tid; t < T_TOK; t += blockDim.x) {
        int e = g_expert[t];
        unsigned peers = __match_any_sync(0xffffffffu, e);
        int leader = __ffs(peers) - 1;
        int rank = __popc(peers & ((1u << lane) - 1));
        int base = 0;
        if (lane == leader) base = atomicAdd(&cur[e], __popc(peers));
        base = __shfl_sync(0xffffffffu, base, leader);
        g_tokpad[base + rank] = t;
    }
}

// ---------------- phase 4: grouped fp16 HMMA GEMM --------------------------
// 128x128 tile, 4 warps of 64x64, 3-stage, 2 CTAs/SM
static constexpr uint32_t OFF_B    = 49152;   // 3 x 16KB A buffers first
static constexpr uint32_t OFF_TOK  = 98304;
static constexpr uint32_t OFF_GATE = 98816;
static constexpr uint32_t SMEM_TOTAL = 99328;

__device__ __forceinline__ void issue_stage(int j, int tid, const int* sTok, int n0,
                                            size_t ebase, uint32_t sbase) {
    int kin = j * BK;
    int buf = j % NSTAGE;
    const __half* Bb = g_wh + ebase;
    uint32_t as = sbase + (uint32_t)buf * 16384;
    uint32_t bs = sbase + OFF_B + (uint32_t)buf * 16384;
#pragma unroll
    for (int i = 0; i < 8; i++) {           // A: 128 rows x 8 chunks, gathered
        int op = tid + i * 128;
        int r = op >> 3, c = op & 7;
        cp16(as + r * 128 + ((c * 16) ^ ((r & 7) << 4)),
             g_xh + (size_t)sTok[r] * HDIM + kin + c * 8);
    }
#pragma unroll
    for (int i = 0; i < 8; i++) {           // B: 128 rows x 8 chunks
        int op = tid + i * 128;
        int r = op >> 3, c = op & 7;
        cp16(bs + r * 128 + ((c * 16) ^ ((r & 7) << 4)),
             Bb + (size_t)(n0 + r) * HDIM + kin + c * 8);
    }
    cp_commit();
}

__global__ __launch_bounds__(128, 2)
void moe_gemm_kernel(const float* __restrict__ eb, float* __restrict__ out) {
    extern __shared__ __align__(1024) char smem[];
    const int m0 = blockIdx.y * BM;
    if (m0 >= g_offpad[NEXP]) return;
    int e = 0;
    while (m0 >= g_offpad[e + 1]) e++;
    const int rows_valid = min(BM, g_offpad[e] + g_counts[e] - m0);
    const int n0 = blockIdx.x * BN;
    const int tid = threadIdx.x;
    const uint32_t sbase = smem_u32(smem);
    const size_t ebase = (size_t)e * HDIM * HDIM;
    int* sTok = (int*)(smem + OFF_TOK);
    float* sGate = (float*)(smem + OFF_GATE);

    {
        int tok = g_tokpad[m0 + tid] & (T_TOK - 1);
        sTok[tid] = tok;
        sGate[tid] = g_gate[tok];
    }
    __syncthreads();

    issue_stage(0, tid, sTok, n0, ebase, sbase);
    issue_stage(1, tid, sTok, n0, ebase, sbase);
    issue_stage(2, tid, sTok, n0, ebase, sbase);

    const int lane = tid & 31, wid = tid >> 5;
    const int warp_m = (wid & 1) * 64;      // 2x2 warp grid, 64x64 tiles
    const int warp_n = (wid >> 1) * 64;
    const int idx = lane & 7, grp = lane >> 3;

    const int arow = warp_m + (grp & 1) * 8 + idx;     // + mt*16, mt 0..3
    const uint32_t axor = (uint32_t)((arow & 7) << 4);
    const uint32_t acsel = (uint32_t)((grp >> 1) * 16);
    const int brow = warp_n + (grp >> 1) * 8 + idx;    // + bt*16, bt 0..3
    const uint32_t bxor = (uint32_t)((brow & 7) << 4);
    const uint32_t bcsel = (uint32_t)((grp & 1) * 16);

    float acc[4][8][4];
#pragma unroll
    for (int i = 0; i < 4; i++)
#pragma unroll
        for (int j = 0; j < 8; j++)
#pragma unroll
            for (int q = 0; q < 4; q++) acc[i][j][q] = 0.f;

    for (int k = 0; k < NITER; k++) {
        cp_wait<2>();
        __syncthreads();
        int buf = k % NSTAGE;
        uint32_t as = sbase + (uint32_t)buf * 16384;
        uint32_t bs = sbase + OFF_B + (uint32_t)buf * 16384;
#pragma unroll
        for (int step = 0; step < 4; step++) {
            uint32_t kc = (uint32_t)(step * 32);
            uint32_t a[4][4], b[4][4];
#pragma unroll
            for (int mt = 0; mt < 4; mt++)
                LDSM4(a[mt], as + (uint32_t)(arow + mt * 16) * 128 + ((kc + acsel) ^ axor));
#pragma unroll
            for (int bt = 0; bt < 4; bt++)
                LDSM4(b[bt], bs + (uint32_t)(brow + bt * 16) * 128 + ((kc + bcsel) ^ bxor));
#pragma unroll
            for (int mt = 0; mt < 4; mt++)
#pragma unroll
                for (int bt = 0; bt < 4; bt++) {
                    MMA16816(acc[mt][2 * bt],     a[mt], b[bt][0], b[bt][1]);
                    MMA16816(acc[mt][2 * bt + 1], a[mt], b[bt][2], b[bt][3]);
                }
        }
        __syncthreads();
        if (k + NSTAGE < NITER) issue_stage(k + NSTAGE, tid, sTok, n0, ebase, sbase);
        else cp_commit();
    }

    // epilogue: warp covers 64 rows x 64 cols
    const float* ebias = eb + (size_t)e * HDIM + n0;
    const int colq = (lane & 3) * 2;
#pragma unroll
    for (int mt = 0; mt < 4; mt++) {
        int r_lo = warp_m + mt * 16 + (lane >> 2);
        int r_hi = r_lo + 8;
        bool v_lo = r_lo < rows_valid, v_hi = r_hi < rows_valid;
        int   t_lo = sTok[r_lo],  t_hi = sTok[r_hi];
        float g_lo = sGate[r_lo], g_hi = sGate[r_hi];
        float* o_lo = out + (size_t)t_lo * HDIM + n0;
        float* o_hi = out + (size_t)t_hi * HDIM + n0;
#pragma unroll
        for (int nt = 0; nt < 8; nt++) {
            int col = warp_n + nt * 8 + colq;
            float2 bv = *reinterpret_cast<const float2*>(ebias + col);
            if (v_lo) {
                float2 v;
                v.x = g_lo * (acc[mt][nt][0] + bv.x);
                v.y = g_lo * (acc[mt][nt][1] + bv.y);
                *reinterpret_cast<float2*>(o_lo + col) = v;
            }
            if (v_hi) {
                float2 v;
                v.x = g_hi * (acc[mt][nt][2] + bv.x);
                v.y = g_hi * (acc[mt][nt][3] + bv.y);
                *reinterpret_cast<float2*>(o_hi + col) = v;
            }
        }
    }
}

// ---------------- launch ----------------
extern "C" void kernel_launch(void* const* d_in, const int* in_sizes, int n_in,
                              void* d_out, int out_size) {
    const float* x  = (const float*)d_in[0];
    const float* rw = (const float*)d_in[1];
    const float* rb = (const float*)d_in[2];
    const float* ew = (const float*)d_in[3];
    const float* eb = (const float*)d_in[4];
    float* out = (float*)d_out;

    cudaFuncSetAttribute(moe_gemm_kernel,
                         cudaFuncAttributeMaxDynamicSharedMemorySize, SMEM_TOTAL);

    convert_w_kernel<<<dim3(32, 16, 8), dim3(32, 8)>>>(ew);   // 1
    router_kernel<<<T_TOK / 8, 256>>>(x, rw, rb);             // 2
    scan_assign_kernel<<<1, 256>>>();                         // 3
    moe_gemm_kernel<<<dim3(HDIM / BN, TPAD / BM), 128, SMEM_TOTAL>>>(eb, out); // 4
}

// round 9
// speedup vs baseline: 1.0274x; 1.0018x over previous
#include <cuda_runtime.h>
#include <cuda_fp16.h>
#include <cstdint>

#define T_TOK 8192
#define HDIM  1024
#define NEXP  8

#define BM 128
#define BN 128
#define BK 64
#define NITER 16        // 1024 / 64
#define NSTAGE 3
#define MAX_MTILES 72   // ceil((8192 + 8*127)/128)

// ---------------- device scratch ----------------
__device__ int   g_expert[T_TOK];
__device__ float g_gate[T_TOK];
__device__ __half g_xh[(size_t)T_TOK * HDIM];               // token order
__device__ __half g_wh[(size_t)NEXP * HDIM * HDIM];         // [e][n][k]

// ---------------- helpers ----------------
__device__ __forceinline__ uint32_t smem_u32(const void* p) {
    uint32_t a;
    asm("{ .reg .u64 t; cvta.to.shared.u64 t, %1; cvt.u32.u64 %0, t; }" : "=r"(a) : "l"(p));
    return a;
}
__device__ __forceinline__ void cp16(uint32_t dst, const void* src) {
    asm volatile("cp.async.cg.shared.global [%0], [%1], 16;" :: "r"(dst), "l"(src));
}
__device__ __forceinline__ void cp_commit() {
    asm volatile("cp.async.commit_group;" ::: "memory");
}
template <int N>
__device__ __forceinline__ void cp_wait() {
    asm volatile("cp.async.wait_group %0;" :: "n"(N) : "memory");
}
#define LDSM4(R, addr) \
    asm volatile("ldmatrix.sync.aligned.m8n8.x4.shared.b16 {%0,%1,%2,%3}, [%4];" \
                 : "=r"((R)[0]), "=r"((R)[1]), "=r"((R)[2]), "=r"((R)[3]) : "r"(addr))
#define MMA16816(D, A, B0, B1) \
    asm volatile("mma.sync.aligned.m16n8k16.row.col.f32.f16.f16.f32 " \
                 "{%0,%1,%2,%3}, {%4,%5,%6,%7}, {%8,%9}, {%0,%1,%2,%3};" \
                 : "+f"((D)[0]), "+f"((D)[1]), "+f"((D)[2]), "+f"((D)[3]) \
                 : "r"((A)[0]), "r"((A)[1]), "r"((A)[2]), "r"((A)[3]), "r"(B0), "r"(B1))

// ============ phase 1: merged prep (router blocks 0..1023, W blocks 1024..5119)
__global__ __launch_bounds__(256)
void prep_kernel(const float* __restrict__ x,
                 const float* __restrict__ rw,
                 const float* __restrict__ rb,
                 const float* __restrict__ ew) {
    if (blockIdx.x < 1024) {
        // ---- router + x fp16 convert: 8 warps, 1 token each ----
        int gwarp = blockIdx.x * 8 + (threadIdx.x >> 5);
        int lane  = threadIdx.x & 31;

        const float* xr = x + (size_t)gwarp * HDIM;
        __half* hp = g_xh + (size_t)gwarp * HDIM;
        float acc[NEXP];
#pragma unroll
        for (int e = 0; e < NEXP; e++) acc[e] = 0.f;

#pragma unroll
        for (int i = 0; i < HDIM / 128; i++) {
            int h = (i * 32 + lane) * 4;
            float4 xv = *reinterpret_cast<const float4*>(xr + h);
            __half2 c0 = __floats2half2_rn(xv.x, xv.y);
            __half2 c1 = __floats2half2_rn(xv.z, xv.w);
            uint2 pk;
            pk.x = *reinterpret_cast<uint32_t*>(&c0);
            pk.y = *reinterpret_cast<uint32_t*>(&c1);
            *reinterpret_cast<uint2*>(hp + h) = pk;

            float xa[4] = {xv.x, xv.y, xv.z, xv.w};
#pragma unroll
            for (int c = 0; c < 4; c++) {
                const float4 w0 = __ldg(reinterpret_cast<const float4*>(rw + (size_t)(h + c) * NEXP));
                const float4 w1 = __ldg(reinterpret_cast<const float4*>(rw + (size_t)(h + c) * NEXP + 4));
                float xc = xa[c];
                acc[0] += xc * w0.x; acc[1] += xc * w0.y;
                acc[2] += xc * w0.z; acc[3] += xc * w0.w;
                acc[4] += xc * w1.x; acc[5] += xc * w1.y;
                acc[6] += xc * w1.z; acc[7] += xc * w1.w;
            }
        }
#pragma unroll
        for (int e = 0; e < NEXP; e++) {
#pragma unroll
            for (int off = 16; off > 0; off >>= 1)
                acc[e] += __shfl_xor_sync(0xffffffffu, acc[e], off);
        }
        if (lane == 0) {
            float logit[NEXP];
            float best = -1e30f;
            int   bi = 0;
#pragma unroll
            for (int e = 0; e < NEXP; e++) {
                logit[e] = acc[e] + rb[e];
                if (logit[e] > best) { best = logit[e]; bi = e; }
            }
            float s = 0.f;
#pragma unroll
            for (int e = 0; e < NEXP; e++) s += expf(logit[e] - best);
            g_expert[gwarp] = bi;
            g_gate[gwarp]   = 1.0f / s;
        }
    } else {
        // ---- W transpose + fp16 convert: [e][k][n] -> [e][n][k] ----
        __shared__ float tile[64][33];
        int bxc = blockIdx.x - 1024;
        int n0 = (bxc & 31) * 32;
        int k0 = ((bxc >> 5) & 15) * 64;
        int e  = bxc >> 9;
        int tx = threadIdx.x & 31, ty = threadIdx.x >> 5;   // 32 x 8
        const float* W = ew + (size_t)e * HDIM * HDIM;
#pragma unroll
        for (int p = 0; p < 8; p++)
            tile[ty + p * 8][tx] = W[(size_t)(k0 + ty + p * 8) * HDIM + n0 + tx];
        __syncthreads();
        int tid = threadIdx.x;
        int l   = tid & 31;        // k-pair: k = 2*l
        int nr  = tid >> 5;        // 0..7
        uint32_t* w32 = reinterpret_cast<uint32_t*>(g_wh);
#pragma unroll
        for (int q = 0; q < 4; q++) {
            int n = nr + q * 8;
            __half2 h = __floats2half2_rn(tile[2 * l][n], tile[2 * l + 1][n]);
            size_t idx = ((size_t)e * HDIM + (n0 + n)) * (HDIM / 2) + (k0 / 2 + l);
            w32[idx] = *reinterpret_cast<uint32_t*>(&h);
        }
    }
}

// ============ phase 2: grouped fp16 HMMA GEMM with self-dispatch ============
static constexpr uint32_t OFF_B    = 49152;   // 3 x 16KB A buffers first
static constexpr uint32_t OFF_TOK  = 98304;   // 128 int
static constexpr uint32_t OFF_GATE = 98816;   // 128 float
static constexpr uint32_t OFF_DISP = 99328;   // s_cnt[8] + s_wsum[8] = 64 B
static constexpr uint32_t SMEM_TOTAL = 99456;

__device__ __forceinline__ void issue_stage(int j, int tid, const int* sTok, int n0,
                                            size_t ebase, uint32_t sbase) {
    int kin = j * BK;
    int buf = j % NSTAGE;
    const __half* Bb = g_wh + ebase;
    uint32_t as = sbase + (uint32_t)buf * 16384;
    uint32_t bs = sbase + OFF_B + (uint32_t)buf * 16384;
#pragma unroll
    for (int i = 0; i < 4; i++) {
        int op = tid + i * 256;
        int r = op >> 3, c = op & 7;
        cp16(as + r * 128 + ((c * 16) ^ ((r & 7) << 4)),
             g_xh + (size_t)sTok[r] * HDIM + kin + c * 8);
    }
#pragma unroll
    for (int i = 0; i < 4; i++) {
        int op = tid + i * 256;
        int r = op >> 3, c = op & 7;
        cp16(bs + r * 128 + ((c * 16) ^ ((r & 7) << 4)),
             Bb + (size_t)(n0 + r) * HDIM + kin + c * 8);
    }
    cp_commit();
}

__global__ __launch_bounds__(256, 2)
void moe_gemm_kernel(const float* __restrict__ eb, float* __restrict__ out) {
    extern __shared__ __align__(1024) char smem[];
    const int tid = threadIdx.x;
    const int lane = tid & 31, wid = tid >> 5;
    const uint32_t sbase = smem_u32(smem);
    int* sTok   = (int*)(smem + OFF_TOK);
    float* sGate = (float*)(smem + OFF_GATE);
    int* s_cnt  = (int*)(smem + OFF_DISP);
    int* s_wsum = (int*)(smem + OFF_DISP + 32);

    // ---------- self-dispatch: counts ----------
    if (tid < NEXP) s_cnt[tid] = 0;
    if (tid < 128) { sTok[tid] = 0; }
    __syncthreads();

    const int tbase32 = tid * 32;
    int lc[NEXP];
#pragma unroll
    for (int e = 0; e < NEXP; e++) lc[e] = 0;
#pragma unroll
    for (int c = 0; c < 8; c++) {
        int4 v = *reinterpret_cast<const int4*>(g_expert + tbase32 + c * 4);
#pragma unroll
        for (int e = 0; e < NEXP; e++)
            lc[e] += (v.x == e) + (v.y == e) + (v.z == e) + (v.w == e);
    }
#pragma unroll
    for (int e = 0; e < NEXP; e++) {
        int v = lc[e];
#pragma unroll
        for (int off = 16; off > 0; off >>= 1)
            v += __shfl_xor_sync(0xffffffffu, v, off);
        if (lane == 0 && v) atomicAdd(&s_cnt[e], v);
    }
    __syncthreads();

    // offsets (every thread, registers)
    int cnt_e[NEXP], offp[NEXP + 1];
    {
        int o = 0;
#pragma unroll
        for (int e = 0; e < NEXP; e++) {
            cnt_e[e] = s_cnt[e];
            offp[e] = o;
            o += (cnt_e[e] + 127) & ~127;
        }
        offp[NEXP] = o;
    }
    const int m0 = blockIdx.y * BM;
    if (m0 >= offp[NEXP]) return;
    int e = 0;
#pragma unroll
    for (int q = 0; q < NEXP - 1; q++) e += (m0 >= offp[q + 1]) ? 1 : 0;
    int myoff = 0, mycnt = 0;
#pragma unroll
    for (int q = 0; q < NEXP; q++) {
        myoff = (e == q) ? offp[q] : myoff;
        mycnt = (e == q) ? cnt_e[q] : mycnt;
    }
    const int r0 = m0 - myoff;
    const int rows_valid = min(BM, mycnt - r0);

    // ---------- self-dispatch: rank scan + emit ----------
    int myc = 0;
#pragma unroll
    for (int q = 0; q < NEXP; q++) myc = (e == q) ? lc[q] : myc;
    int incl = myc;
#pragma unroll
    for (int d = 1; d < 32; d <<= 1) {
        int n = __shfl_up_sync(0xffffffffu, incl, d);
        if (lane >= d) incl += n;
    }
    if (lane == 31) s_wsum[wid] = incl;
    __syncthreads();
    if (tid == 0) {
        int a = 0;
#pragma unroll
        for (int w = 0; w < 8; w++) { int t = s_wsum[w]; s_wsum[w] = a; a += t; }
    }
    __syncthreads();
    int rank = s_wsum[wid] + incl - myc;   // exclusive rank of this thread's first match
#pragma unroll
    for (int c = 0; c < 8; c++) {
        int4 v = *reinterpret_cast<const int4*>(g_expert + tbase32 + c * 4);
        int ta[4] = {v.x, v.y, v.z, v.w};
#pragma unroll
        for (int j = 0; j < 4; j++) {
            if (ta[j] == e) {
                int rr = rank - r0;
                if (rr >= 0 && rr < BM) sTok[rr] = tbase32 + c * 4 + j;
                rank++;
            }
        }
    }
    __syncthreads();
    if (tid < 128) sGate[tid] = g_gate[sTok[tid]];
    __syncthreads();

    // ---------- GEMM (round-6 geometry: 8 warps, 32x64 tiles, 3-stage) ------
    const int n0 = blockIdx.x * BN;
    const size_t ebase = (size_t)e * HDIM * HDIM;

    issue_stage(0, tid, sTok, n0, ebase, sbase);
    issue_stage(1, tid, sTok, n0, ebase, sbase);
    issue_stage(2, tid, sTok, n0, ebase, sbase);

    const int warp_m = (wid >> 1) * 32;
    const int warp_n = (wid & 1) * 64;
    const int idx = lane & 7, grp = lane >> 3;

    const int arow = warp_m + (grp & 1) * 8 + idx;
    const uint32_t axor = (uint32_t)((arow & 7) << 4);
    const uint32_t acsel = (uint32_t)((grp >> 1) * 16);
    const int brow = warp_n + (grp >> 1) * 8 + idx;
    const uint32_t bxor = (uint32_t)((brow & 7) << 4);
    const uint32_t bcsel = (uint32_t)((grp & 1) * 16);

    float acc[2][8][4];
#pragma unroll
    for (int i = 0; i < 2; i++)
#pragma unroll
        for (int j = 0; j < 8; j++)
#pragma unroll
            for (int q = 0; q < 4; q++) acc[i][j][q] = 0.f;

    for (int k = 0; k < NITER; k++) {
        cp_wait<2>();
        __syncthreads();
        int buf = k % NSTAGE;
        uint32_t as = sbase + (uint32_t)buf * 16384;
        uint32_t bs = sbase + OFF_B + (uint32_t)buf * 16384;
#pragma unroll
        for (int step = 0; step < 4; step++) {
            uint32_t kc = (uint32_t)(step * 32);
            uint32_t a[2][4], b[4][4];
#pragma unroll
            for (int mt = 0; mt < 2; mt++)
                LDSM4(a[mt], as + (uint32_t)(arow + mt * 16) * 128 + ((kc + acsel) ^ axor));
#pragma unroll
            for (int bt = 0; bt < 4; bt++)
                LDSM4(b[bt], bs + (uint32_t)(brow + bt * 16) * 128 + ((kc + bcsel) ^ bxor));
#pragma unroll
            for (int mt = 0; mt < 2; mt++)
#pragma unroll
                for (int bt = 0; bt < 4; bt++) {
                    MMA16816(acc[mt][2 * bt],     a[mt], b[bt][0], b[bt][1]);
                    MMA16816(acc[mt][2 * bt + 1], a[mt], b[bt][2], b[bt][3]);
                }
        }
        __syncthreads();
        if (k + NSTAGE < NITER) issue_stage(k + NSTAGE, tid, sTok, n0, ebase, sbase);
        else cp_commit();
    }

    // ---------- epilogue ----------
    const float* ebias = eb + (size_t)e * HDIM + n0;
    const int colq = (lane & 3) * 2;
#pragma unroll
    for (int mt = 0; mt < 2; mt++) {
        int r_lo = warp_m + mt * 16 + (lane >> 2);
        int r_hi = r_lo + 8;
        bool v_lo = r_lo < rows_valid, v_hi = r_hi < rows_valid;
        int   t_lo = sTok[r_lo],  t_hi = sTok[r_hi];
        float g_lo = sGate[r_lo], g_hi = sGate[r_hi];
        float* o_lo = out + (size_t)t_lo * HDIM + n0;
        float* o_hi = out + (size_t)t_hi * HDIM + n0;
#pragma unroll
        for (int nt = 0; nt < 8; nt++) {
            int col = warp_n + nt * 8 + colq;
            float2 bv = *reinterpret_cast<const float2*>(ebias + col);
            if (v_lo) {
                float2 v;
                v.x = g_lo * (acc[mt][nt][0] + bv.x);
                v.y = g_lo * (acc[mt][nt][1] + bv.y);
                *reinterpret_cast<float2*>(o_lo + col) = v;
            }
            if (v_hi) {
                float2 v;
                v.x = g_hi * (acc[mt][nt][2] + bv.x);
                v.y = g_hi * (acc[mt][nt][3] + bv.y);
                *reinterpret_cast<float2*>(o_hi + col) = v;
            }
        }
    }
}

// ---------------- launch ----------------
extern "C" void kernel_launch(void* const* d_in, const int* in_sizes, int n_in,
                              void* d_out, int out_size) {
    const float* x  = (const float*)d_in[0];
    const float* rw = (const float*)d_in[1];
    const float* rb = (const float*)d_in[2];
    const float* ew = (const float*)d_in[3];
    const float* eb = (const float*)d_in[4];
    float* out = (float*)d_out;

    cudaFuncSetAttribute(moe_gemm_kernel,
                         cudaFuncAttributeMaxDynamicSharedMemorySize, SMEM_TOTAL);

    prep_kernel<<<5120, 256>>>(x, rw, rb, ew);                                 // 1
    moe_gemm_kernel<<<dim3(HDIM / BN, MAX_MTILES), 256, SMEM_TOTAL>>>(eb, out); // 2
}

// round 10
// speedup vs baseline: 1.5877x; 1.5453x over previous
#include <cuda_runtime.h>
#include <cuda_fp16.h>
#include <cstdint>

#define T_TOK 8192
#define HDIM  1024
#define NEXP  8
#define TPAD  (T_TOK + NEXP*128)

#define BM 128
#define BN 128
#define BK 64
#define NITER 16        // 1024 / 64
#define NSTAGE 3

// ---------------- device scratch ----------------
__device__ int   g_counts[NEXP];
__device__ int   g_offpad[NEXP + 1];
__device__ int   g_expert[T_TOK];
__device__ float g_gate[T_TOK];
__device__ int   g_tokpad[TPAD];
__device__ int   g_done;                                    // router-completion ticket
__device__ __half g_xh[(size_t)T_TOK * HDIM];               // token order
__device__ __half g_wh[(size_t)NEXP * HDIM * HDIM];         // [e][n][k]

// ---------------- helpers ----------------
__device__ __forceinline__ uint32_t smem_u32(const void* p) {
    uint32_t a;
    asm("{ .reg .u64 t; cvta.to.shared.u64 t, %1; cvt.u32.u64 %0, t; }" : "=r"(a) : "l"(p));
    return a;
}
__device__ __forceinline__ void cp16(uint32_t dst, const void* src) {
    asm volatile("cp.async.cg.shared.global [%0], [%1], 16;" :: "r"(dst), "l"(src));
}
__device__ __forceinline__ void cp_commit() {
    asm volatile("cp.async.commit_group;" ::: "memory");
}
template <int N>
__device__ __forceinline__ void cp_wait() {
    asm volatile("cp.async.wait_group %0;" :: "n"(N) : "memory");
}
#define LDSM4(R, addr) \
    asm volatile("ldmatrix.sync.aligned.m8n8.x4.shared.b16 {%0,%1,%2,%3}, [%4];" \
                 : "=r"((R)[0]), "=r"((R)[1]), "=r"((R)[2]), "=r"((R)[3]) : "r"(addr))
#define MMA16816(D, A, B0, B1) \
    asm volatile("mma.sync.aligned.m16n8k16.row.col.f32.f16.f16.f32 " \
                 "{%0,%1,%2,%3}, {%4,%5,%6,%7}, {%8,%9}, {%0,%1,%2,%3};" \
                 : "+f"((D)[0]), "+f"((D)[1]), "+f"((D)[2]), "+f"((D)[3]) \
                 : "r"((A)[0]), "r"((A)[1]), "r"((A)[2]), "r"((A)[3]), "r"(B0), "r"(B1))

// ============ phase 1: merged prep ============
// blocks 0..1023   : router + x fp16 convert (rw staged in SMEM)
// blocks 1024..5119: W transpose + fp16 convert
// last router block to finish also performs the token dispatch (overlapped)
__global__ __launch_bounds__(256)
void prep_kernel(const float* __restrict__ x,
                 const float* __restrict__ rw,
                 const float* __restrict__ rb,
                 const float* __restrict__ ew) {
    __shared__ float rws[NEXP][1028];    // transposed router weights, conflict-free
    __shared__ float tile[64][33];       // W-transpose staging
    __shared__ int s_cnt[NEXP];
    __shared__ int s_cur[NEXP];
    __shared__ int s_flag;

    const int tid = threadIdx.x;
    const int lane = tid & 31;

    if (blockIdx.x < 1024) {
        // ---- stage rw[h][e] -> rws[e][h] ----
#pragma unroll
        for (int i = 0; i < 32; i++) {
            int idx = tid + i * 256;            // 8192 elements
            rws[idx & 7][idx >> 3] = rw[idx];
        }
        __syncthreads();

        // ---- router + fp16 convert: 8 warps, 1 token each ----
        int gwarp = blockIdx.x * 8 + (tid >> 5);
        const float* xr = x + (size_t)gwarp * HDIM;
        __half* hp = g_xh + (size_t)gwarp * HDIM;
        float acc[NEXP];
#pragma unroll
        for (int e = 0; e < NEXP; e++) acc[e] = 0.f;

#pragma unroll
        for (int i = 0; i < HDIM / 128; i++) {
            int h = (i * 32 + lane) * 4;
            float4 xv = *reinterpret_cast<const float4*>(xr + h);
            __half2 c0 = __floats2half2_rn(xv.x, xv.y);
            __half2 c1 = __floats2half2_rn(xv.z, xv.w);
            uint2 pk;
            pk.x = *reinterpret_cast<uint32_t*>(&c0);
            pk.y = *reinterpret_cast<uint32_t*>(&c1);
            *reinterpret_cast<uint2*>(hp + h) = pk;
#pragma unroll
            for (int e = 0; e < NEXP; e++) {
                float4 wv = *reinterpret_cast<const float4*>(&rws[e][h]);
                acc[e] += xv.x * wv.x + xv.y * wv.y + xv.z * wv.z + xv.w * wv.w;
            }
        }
#pragma unroll
        for (int e = 0; e < NEXP; e++) {
#pragma unroll
            for (int off = 16; off > 0; off >>= 1)
                acc[e] += __shfl_xor_sync(0xffffffffu, acc[e], off);
        }
        if (lane == 0) {
            float logit[NEXP];
            float best = -1e30f;
            int   bi = 0;
#pragma unroll
            for (int e = 0; e < NEXP; e++) {
                logit[e] = acc[e] + rb[e];
                if (logit[e] > best) { best = logit[e]; bi = e; }
            }
            float s = 0.f;
#pragma unroll
            for (int e = 0; e < NEXP; e++) s += expf(logit[e] - best);
            g_expert[gwarp] = bi;
            g_gate[gwarp]   = 1.0f / s;
        }

        // ---- completion ticket; last router block runs dispatch ----
        __syncthreads();
        if (tid == 0) {
            __threadfence();
            int old = atomicAdd(&g_done, 1);
            s_flag = (old == 1023) ? 1 : 0;
        }
        __syncthreads();
        if (!s_flag) return;

        // ---- dispatch (single block, overlapped with W blocks) ----
        __threadfence();   // acquire g_expert written by other blocks
        if (tid < NEXP) s_cnt[tid] = 0;
        __syncthreads();
        int local[NEXP];
#pragma unroll
        for (int e = 0; e < NEXP; e++) local[e] = 0;
        for (int t = tid; t < T_TOK; t += 256) local[g_expert[t]]++;
#pragma unroll
        for (int e = 0; e < NEXP; e++)
            if (local[e]) atomicAdd(&s_cnt[e], local[e]);
        __syncthreads();
        if (tid == 0) {
            int o = 0;
#pragma unroll
            for (int e = 0; e < NEXP; e++) {
                g_counts[e] = s_cnt[e];
                g_offpad[e] = o;
                s_cur[e] = o;
                o += ((s_cnt[e] + 127) >> 7) << 7;
            }
            g_offpad[NEXP] = o;
            g_done = 0;    // reset ticket for next graph replay
        }
        __syncthreads();
        for (int t = tid; t < T_TOK; t += 256) {
            int e = g_expert[t];
            unsigned peers = __match_any_sync(0xffffffffu, e);
            int leader = __ffs(peers) - 1;
            int rank = __popc(peers & ((1u << lane) - 1));
            int base = 0;
            if (lane == leader) base = atomicAdd(&s_cur[e], __popc(peers));
            base = __shfl_sync(0xffffffffu, base, leader);
            g_tokpad[base + rank] = t;
        }
    } else {
        // ---- W transpose + fp16 convert ----
        int bxc = blockIdx.x - 1024;
        int n0 = (bxc & 31) * 32;
        int k0 = ((bxc >> 5) & 15) * 64;
        int e  = bxc >> 9;
        int tx = tid & 31, ty = tid >> 5;   // 32 x 8
        const float* W = ew + (size_t)e * HDIM * HDIM;
#pragma unroll
        for (int p = 0; p < 8; p++)
            tile[ty + p * 8][tx] = W[(size_t)(k0 + ty + p * 8) * HDIM + n0 + tx];
        __syncthreads();
        int l  = tid & 31;        // k-pair: k = 2*l
        int nr = tid >> 5;        // 0..7
        uint32_t* w32 = reinterpret_cast<uint32_t*>(g_wh);
#pragma unroll
        for (int q = 0; q < 4; q++) {
            int n = nr + q * 8;
            __half2 h = __floats2half2_rn(tile[2 * l][n], tile[2 * l + 1][n]);
            size_t idx = ((size_t)e * HDIM + (n0 + n)) * (HDIM / 2) + (k0 / 2 + l);
            w32[idx] = *reinterpret_cast<uint32_t*>(&h);
        }
    }
}

// ============ phase 2: grouped fp16 HMMA GEMM (round-6 geometry) ============
static constexpr uint32_t OFF_B    = 49152;   // 3 x 16KB A buffers first
static constexpr uint32_t OFF_TOK  = 98304;
static constexpr uint32_t OFF_GATE = 98816;
static constexpr uint32_t SMEM_TOTAL = 99328;

__device__ __forceinline__ void issue_stage(int j, int tid, const int* sTok, int n0,
                                            size_t ebase, uint32_t sbase) {
    int kin = j * BK;
    int buf = j % NSTAGE;
    const __half* Bb = g_wh + ebase;
    uint32_t as = sbase + (uint32_t)buf * 16384;
    uint32_t bs = sbase + OFF_B + (uint32_t)buf * 16384;
#pragma unroll
    for (int i = 0; i < 4; i++) {
        int op = tid + i * 256;
        int r = op >> 3, c = op & 7;
        cp16(as + r * 128 + ((c * 16) ^ ((r & 7) << 4)),
             g_xh + (size_t)sTok[r] * HDIM + kin + c * 8);
    }
#pragma unroll
    for (int i = 0; i < 4; i++) {
        int op = tid + i * 256;
        int r = op >> 3, c = op & 7;
        cp16(bs + r * 128 + ((c * 16) ^ ((r & 7) << 4)),
             Bb + (size_t)(n0 + r) * HDIM + kin + c * 8);
    }
    cp_commit();
}

__global__ __launch_bounds__(256, 2)
void moe_gemm_kernel(const float* __restrict__ eb, float* __restrict__ out) {
    extern __shared__ __align__(1024) char smem[];
    const int m0 = blockIdx.y * BM;
    if (m0 >= g_offpad[NEXP]) return;
    int e = 0;
    while (m0 >= g_offpad[e + 1]) e++;
    const int rows_valid = min(BM, g_offpad[e] + g_counts[e] - m0);
    const int n0 = blockIdx.x * BN;
    const int tid = threadIdx.x;
    const uint32_t sbase = smem_u32(smem);
    const size_t ebase = (size_t)e * HDIM * HDIM;
    int* sTok = (int*)(smem + OFF_TOK);
    float* sGate = (float*)(smem + OFF_GATE);

    if (tid < 128) {
        int tok = g_tokpad[m0 + tid] & (T_TOK - 1);
        sTok[tid] = tok;
        sGate[tid] = g_gate[tok];
    }
    __syncthreads();

    issue_stage(0, tid, sTok, n0, ebase, sbase);
    issue_stage(1, tid, sTok, n0, ebase, sbase);
    issue_stage(2, tid, sTok, n0, ebase, sbase);

    const int lane = tid & 31, wid = tid >> 5;
    const int warp_m = (wid >> 1) * 32;
    const int warp_n = (wid & 1) * 64;
    const int idx = lane & 7, grp = lane >> 3;

    const int arow = warp_m + (grp & 1) * 8 + idx;
    const uint32_t axor = (uint32_t)((arow & 7) << 4);
    const uint32_t acsel = (uint32_t)((grp >> 1) * 16);
    const int brow = warp_n + (grp >> 1) * 8 + idx;
    const uint32_t bxor = (uint32_t)((brow & 7) << 4);
    const uint32_t bcsel = (uint32_t)((grp & 1) * 16);

    float acc[2][8][4];
#pragma unroll
    for (int i = 0; i < 2; i++)
#pragma unroll
        for (int j = 0; j < 8; j++)
#pragma unroll
            for (int q = 0; q < 4; q++) acc[i][j][q] = 0.f;

    for (int k = 0; k < NITER; k++) {
        cp_wait<2>();
        __syncthreads();
        int buf = k % NSTAGE;
        uint32_t as = sbase + (uint32_t)buf * 16384;
        uint32_t bs = sbase + OFF_B + (uint32_t)buf * 16384;
#pragma unroll
        for (int step = 0; step < 4; step++) {
            uint32_t kc = (uint32_t)(step * 32);
            uint32_t a[2][4], b[4][4];
#pragma unroll
            for (int mt = 0; mt < 2; mt++)
                LDSM4(a[mt], as + (uint32_t)(arow + mt * 16) * 128 + ((kc + acsel) ^ axor));
#pragma unroll
            for (int bt = 0; bt < 4; bt++)
                LDSM4(b[bt], bs + (uint32_t)(brow + bt * 16) * 128 + ((kc + bcsel) ^ bxor));
#pragma unroll
            for (int mt = 0; mt < 2; mt++)
#pragma unroll
                for (int bt = 0; bt < 4; bt++) {
                    MMA16816(acc[mt][2 * bt],     a[mt], b[bt][0], b[bt][1]);
                    MMA16816(acc[mt][2 * bt + 1], a[mt], b[bt][2], b[bt][3]);
                }
        }
        __syncthreads();
        if (k + NSTAGE < NITER) issue_stage(k + NSTAGE, tid, sTok, n0, ebase, sbase);
        else cp_commit();
    }

    // epilogue
    const float* ebias = eb + (size_t)e * HDIM + n0;
    const int colq = (lane & 3) * 2;
#pragma unroll
    for (int mt = 0; mt < 2; mt++) {
        int r_lo = warp_m + mt * 16 + (lane >> 2);
        int r_hi = r_lo + 8;
        bool v_lo = r_lo < rows_valid, v_hi = r_hi < rows_valid;
        int   t_lo = sTok[r_lo],  t_hi = sTok[r_hi];
        float g_lo = sGate[r_lo], g_hi = sGate[r_hi];
        float* o_lo = out + (size_t)t_lo * HDIM + n0;
        float* o_hi = out + (size_t)t_hi * HDIM + n0;
#pragma unroll
        for (int nt = 0; nt < 8; nt++) {
            int col = warp_n + nt * 8 + colq;
            float2 bv = *reinterpret_cast<const float2*>(ebias + col);
            if (v_lo) {
                float2 v;
                v.x = g_lo * (acc[mt][nt][0] + bv.x);
                v.y = g_lo * (acc[mt][nt][1] + bv.y);
                *reinterpret_cast<float2*>(o_lo + col) = v;
            }
            if (v_hi) {
                float2 v;
                v.x = g_hi * (acc[mt][nt][2] + bv.x);
                v.y = g_hi * (acc[mt][nt][3] + bv.y);
                *reinterpret_cast<float2*>(o_hi + col) = v;
            }
        }
    }
}

// ---------------- launch ----------------
extern "C" void kernel_launch(void* const* d_in, const int* in_sizes, int n_in,
                              void* d_out, int out_size) {
    const float* x  = (const float*)d_in[0];
    const float* rw = (const float*)d_in[1];
    const float* rb = (const float*)d_in[2];
    const float* ew = (const float*)d_in[3];
    const float* eb = (const float*)d_in[4];
    float* out = (float*)d_out;

    cudaFuncSetAttribute(moe_gemm_kernel,
                         cudaFuncAttributeMaxDynamicSharedMemorySize, SMEM_TOTAL);

    prep_kernel<<<5120, 256>>>(x, rw, rb, ew);                                  // 1
    moe_gemm_kernel<<<dim3(HDIM / BN, TPAD / BM), 256, SMEM_TOTAL>>>(eb, out);  // 2
}